// round 12
// baseline (speedup 1.0000x reference)
#include <cuda_runtime.h>
#include <math.h>

#define NMAX 65536
#define FULL 0xFFFFFFFFu

// Scratch (static __device__ — no allocation). Per (type t, edge-type g):
// per-node per-head scalars, softmax accumulators.
__device__ float4 g_ssrc[3][2][NMAX];
__device__ float4 g_sdst[3][2][NMAX];
__device__ float4 g_p   [3][2][NMAX];
__device__ float4 g_den [3][2][NMAX];
__device__ float4 g_num [3][2][NMAX];
__device__ float  g_base[3][NMAX];

// Small composed parameter tensors
__device__ float g_v[2][3][128][4];      // [g][kind(src,dst,p)][j][h] = per-head Wg@att
__device__ float g_M[3][2][3][128][4];   // [t][g][kind][i][h] = W_t @ v
__device__ float g_wt[3][128];           // W_t @ W_cls
__device__ float g_c[3][2][3][4];        // b_t @ v
__device__ float g_basec[3];             // b_t @ W_cls
__device__ float g_bgw[2];               // bg_g @ W_cls

// ---------------------------------------------------------------------------
// prep1: v[g][k][j][h] = sum_c Wg_g[j, h*32+c] * att[h*32+c]
// ---------------------------------------------------------------------------
__global__ void prep1(const float* __restrict__ Wg0, const float* __restrict__ as0,
                      const float* __restrict__ ad0, const float* __restrict__ bg0,
                      const float* __restrict__ Wg1, const float* __restrict__ as1,
                      const float* __restrict__ ad1, const float* __restrict__ bg1,
                      const float* __restrict__ wcls)
{
    int tid = threadIdx.x;
    for (int i = tid; i < 2 * 3 * 128 * 4; i += blockDim.x) {
        int h = i & 3;
        int j = (i >> 2) & 127;
        int k = (i >> 9) % 3;
        int g = i / 1536;
        const float* Wg = g ? Wg1 : Wg0;
        const float* av = (k == 0) ? (g ? as1 : as0)
                        : (k == 1) ? (g ? ad1 : ad0)
                        : wcls;
        const float* wrow = Wg + j * 128 + h * 32;
        const float* arow = av + h * 32;
        float sum = 0.f;
        #pragma unroll 8
        for (int c = 0; c < 32; c++) sum += wrow[c] * arow[c];
        g_v[g][k][j][h] = sum;
    }
    if (tid < 2) {
        const float* bg = tid ? bg1 : bg0;
        float s = 0.f;
        for (int j = 0; j < 128; j++) s += bg[j] * wcls[j];
        g_bgw[tid] = s;
    }
}

// ---------------------------------------------------------------------------
// prep2: M[t][g][k] = W_t @ v[g][k];  wt = W_t @ wcls;  c = b_t @ v;  basec = b_t @ wcls
// ---------------------------------------------------------------------------
__global__ void prep2(const float* __restrict__ W0, const float* __restrict__ b0,
                      const float* __restrict__ W1, const float* __restrict__ b1,
                      const float* __restrict__ W2, const float* __restrict__ b2,
                      const float* __restrict__ wcls,
                      int d0, int d1, int d2)
{
    int id = blockIdx.x * blockDim.x + threadIdx.x;
    int din[3] = {d0, d1, d2};
    const float* W[3] = {W0, W1, W2};
    const float* b[3] = {b0, b1, b2};
    if (id < 9216) {
        int h = id & 3;
        int i = (id >> 2) & 127;
        int k = (id >> 9) % 3;
        int g = (id / 1536) % 2;
        int t = id / 3072;
        if (i < din[t]) {
            const float* Wr = W[t] + i * 128;
            float sum = 0.f;
            #pragma unroll 8
            for (int j = 0; j < 128; j++) sum += Wr[j] * g_v[g][k][j][h];
            g_M[t][g][k][i][h] = sum;
        }
    } else if (id < 9216 + 384) {
        int r = id - 9216;
        int i = r & 127; int t = r >> 7;
        if (i < din[t]) {
            const float* Wr = W[t] + i * 128;
            float s = 0.f;
            #pragma unroll 8
            for (int j = 0; j < 128; j++) s += Wr[j] * wcls[j];
            g_wt[t][i] = s;
        }
    } else if (id < 9216 + 384 + 72) {
        int r = id - 9600;
        int h = r & 3; int k = (r >> 2) % 3; int g = (r / 12) % 2; int t = r / 24;
        float s = 0.f;
        for (int j = 0; j < 128; j++) s += b[t][j] * g_v[g][k][j][h];
        g_c[t][g][k][h] = s;
    } else if (id < 9216 + 384 + 72 + 3) {
        int t = id - 9672;
        float s = 0.f;
        for (int j = 0; j < 128; j++) s += b[t][j] * wcls[j];
        g_basec[t] = s;
    }
}

// ---------------------------------------------------------------------------
// nodeK: fused over t via blockIdx.y. Warp per node: 25 dot products of x_n
// against composed matrices (in shared), warp shfl-reduce, self-loop init.
// ---------------------------------------------------------------------------
__global__ void nodeK(const float* __restrict__ x0, const float* __restrict__ x1,
                      const float* __restrict__ x2,
                      int d0, int d1, int d2, int N)
{
    int t = blockIdx.y;
    const float* x = (t == 0) ? x0 : (t == 1) ? x1 : x2;
    int din = (t == 0) ? d0 : (t == 1) ? d1 : d2;

    __shared__ float sM[25][128];
    int tid = threadIdx.x;
    for (int i = tid; i < 25 * 128; i += blockDim.x) {
        int o = i >> 7; int j = i & 127;
        float v = 0.f;
        if (j < din) {
            if (o < 24) {
                int g = o / 12; int k = (o % 12) >> 2; int h = o & 3;
                v = g_M[t][g][k][j][h];
            } else {
                v = g_wt[t][j];
            }
        }
        sM[o][j] = v;
    }
    __syncthreads();

    int warp = tid >> 5, lane = tid & 31;
    int n = blockIdx.x * 8 + warp;
    if (n >= N) return;

    float4 xv = make_float4(0.f, 0.f, 0.f, 0.f);
    if (4 * lane < din)
        xv = ((const float4*)(x + (size_t)n * din))[lane];

    float acc[25];
    #pragma unroll
    for (int o = 0; o < 25; o++) {
        float4 m = ((const float4*)sM[o])[lane];
        acc[o] = xv.x * m.x + xv.y * m.y + xv.z * m.z + xv.w * m.w;
    }
    #pragma unroll
    for (int o = 0; o < 25; o++) {
        float v = acc[o];
        v += __shfl_xor_sync(FULL, v, 16);
        v += __shfl_xor_sync(FULL, v, 8);
        v += __shfl_xor_sync(FULL, v, 4);
        v += __shfl_xor_sync(FULL, v, 2);
        v += __shfl_xor_sync(FULL, v, 1);
        acc[o] = v;
    }

    if (lane == 0) {
        #pragma unroll
        for (int g = 0; g < 2; g++) {
            float ss[4], sd[4], pv[4], de[4], nu[4];
            #pragma unroll
            for (int h = 0; h < 4; h++) {
                ss[h] = acc[g * 12 + h]     + g_c[t][g][0][h];
                sd[h] = acc[g * 12 + 4 + h] + g_c[t][g][1][h];
                pv[h] = acc[g * 12 + 8 + h] + g_c[t][g][2][h];
                float e = ss[h] + sd[h];
                e = e > 0.f ? e : 0.2f * e;   // leaky_relu(0.2)
                float ex = __expf(e);
                de[h] = ex;
                nu[h] = ex * pv[h];
            }
            g_ssrc[t][g][n] = make_float4(ss[0], ss[1], ss[2], ss[3]);
            g_sdst[t][g][n] = make_float4(sd[0], sd[1], sd[2], sd[3]);
            g_p[t][g][n]    = make_float4(pv[0], pv[1], pv[2], pv[3]);
            g_den[t][g][n]  = make_float4(de[0], de[1], de[2], de[3]);  // self-loop init
            g_num[t][g][n]  = make_float4(nu[0], nu[1], nu[2], nu[3]);
        }
        g_base[t][n] = acc[24] + g_basec[t];
    }
}

// ---------------------------------------------------------------------------
// edgeK: fused over g via blockIdx.y. One pass: exp(leaky_relu(ssrc[s]+sdst[d])),
// vector RED into num/den. All per-node arrays L2-resident. Grid-stride.
// ---------------------------------------------------------------------------
__global__ void edgeK(const int* __restrict__ ei0, int E0,
                      const int* __restrict__ ei1, int E1)
{
    int g = blockIdx.y;
    const int* ei = g ? ei1 : ei0;
    int E = g ? E1 : E0;
    for (int e = blockIdx.x * blockDim.x + threadIdx.x; e < E;
         e += gridDim.x * blockDim.x) {
        int s = __ldg(&ei[e]);
        int d = __ldg(&ei[E + e]);
        #pragma unroll
        for (int t = 0; t < 3; t++) {
            float4 a  = __ldg(&g_ssrc[t][g][s]);
            float4 b  = __ldg(&g_sdst[t][g][d]);
            float4 pp = __ldg(&g_p[t][g][s]);
            float e0 = a.x + b.x, e1 = a.y + b.y, e2 = a.z + b.z, e3 = a.w + b.w;
            e0 = e0 > 0.f ? e0 : 0.2f * e0;
            e1 = e1 > 0.f ? e1 : 0.2f * e1;
            e2 = e2 > 0.f ? e2 : 0.2f * e2;
            e3 = e3 > 0.f ? e3 : 0.2f * e3;
            float x0 = __expf(e0), x1 = __expf(e1), x2 = __expf(e2), x3 = __expf(e3);
            atomicAdd(&g_den[t][g][d], make_float4(x0, x1, x2, x3));
            atomicAdd(&g_num[t][g][d], make_float4(x0 * pp.x, x1 * pp.y, x2 * pp.z, x3 * pp.w));
        }
    }
}

// ---------------------------------------------------------------------------
// finalK: out[t*N+n] = sigmoid(base + sum_g (bg.w + sum_h num/den) + b_cls)
// ---------------------------------------------------------------------------
__global__ void finalK(float* __restrict__ out, const float* __restrict__ bcls, int N)
{
    int id = blockIdx.x * blockDim.x + threadIdx.x;
    if (id >= 3 * N) return;
    int t = id / N, n = id - t * N;
    float z = g_base[t][n] + bcls[0];
    #pragma unroll
    for (int g = 0; g < 2; g++) {
        float4 nu = g_num[t][g][n];
        float4 de = g_den[t][g][n];
        z += g_bgw[g] + nu.x / de.x + nu.y / de.y + nu.z / de.z + nu.w / de.w;
    }
    out[id] = 1.f / (1.f + __expf(-z));
}

extern "C" void kernel_launch(void* const* d_in, const int* in_sizes, int n_in,
                              void* d_out, int out_size)
{
    const float* x_acc = (const float*)d_in[0];
    const float* x_cus = (const float*)d_in[1];
    const float* x_txn = (const float*)d_in[2];
    // d_in[3] = ei_transacts: dead code in the reference
    const int*   ei_ow = (const int*)d_in[4];
    const int*   ei_sh = (const int*)d_in[5];
    const float* W_acc = (const float*)d_in[6];  const float* b_acc = (const float*)d_in[7];
    const float* W_cus = (const float*)d_in[8];  const float* b_cus = (const float*)d_in[9];
    const float* W_txn = (const float*)d_in[10]; const float* b_txn = (const float*)d_in[11];
    const float* Wg_ow = (const float*)d_in[12]; const float* as_ow = (const float*)d_in[13];
    const float* ad_ow = (const float*)d_in[14]; const float* bg_ow = (const float*)d_in[15];
    const float* Wg_sh = (const float*)d_in[16]; const float* as_sh = (const float*)d_in[17];
    const float* ad_sh = (const float*)d_in[18]; const float* bg_sh = (const float*)d_in[19];
    const float* W_cls = (const float*)d_in[20]; const float* b_cls = (const float*)d_in[21];
    float* out = (float*)d_out;

    int HIDv = in_sizes[7];               // 128
    int d0 = in_sizes[6] / HIDv;          // 64
    int d1 = in_sizes[8] / HIDv;          // 32
    int d2 = in_sizes[10] / HIDv;         // 128
    int N  = in_sizes[0] / d0;            // 50000
    int E_ow = in_sizes[4] / 2;
    int E_sh = in_sizes[5] / 2;

    prep1<<<1, 256>>>(Wg_ow, as_ow, ad_ow, bg_ow, Wg_sh, as_sh, ad_sh, bg_sh, W_cls);
    prep2<<<(9675 + 127) / 128, 128>>>(W_acc, b_acc, W_cus, b_cus, W_txn, b_txn, W_cls,
                                       d0, d1, d2);
    dim3 ngrid((N + 7) / 8, 3);
    nodeK<<<ngrid, 256>>>(x_acc, x_cus, x_txn, d0, d1, d2, N);
    dim3 egrid(1184, 2);
    edgeK<<<egrid, 256>>>(ei_ow, E_ow, ei_sh, E_sh);
    finalK<<<(3 * N + 255) / 256, 256>>>(out, b_cls, N);
}

// round 14
// speedup vs baseline: 1.7377x; 1.7377x over previous
#include <cuda_runtime.h>
#include <math.h>

#define NMAX 65536
#define FULL 0xFFFFFFFFu

// Scratch (static __device__ — no allocation). Per (type t, edge-type g):
// per-node per-head scalars, softmax accumulators.
__device__ float4 g_ssrc[3][2][NMAX];
__device__ float4 g_sdst[3][2][NMAX];
__device__ float4 g_p   [3][2][NMAX];
__device__ float4 g_den [3][2][NMAX];
__device__ float4 g_num [3][2][NMAX];
__device__ float  g_base[3][NMAX];

// Small composed parameter tensors
__device__ float g_v[2][3][128][4];      // [g][kind(src,dst,p)][j][h] = per-head Wg@att
// g_Mt[t][o][j]: o = g*12 + k*4 + h for o<24; o==24 = W_t@W_cls. Zero-padded j>=din.
__device__ __align__(16) float g_Mt[3][25][128];
__device__ float g_c[3][2][3][4];        // b_t @ v
__device__ float g_basec[3];             // b_t @ W_cls
__device__ float g_bgw[2];               // bg_g @ W_cls

// ---------------------------------------------------------------------------
// prep1: v[g][k][j][h] = sum_c Wg_g[j, h*32+c] * att[h*32+c]
// ---------------------------------------------------------------------------
__global__ void prep1(const float* __restrict__ Wg0, const float* __restrict__ as0,
                      const float* __restrict__ ad0, const float* __restrict__ bg0,
                      const float* __restrict__ Wg1, const float* __restrict__ as1,
                      const float* __restrict__ ad1, const float* __restrict__ bg1,
                      const float* __restrict__ wcls)
{
    int tid = threadIdx.x;
    for (int i = tid; i < 2 * 3 * 128 * 4; i += blockDim.x) {
        int h = i & 3;
        int j = (i >> 2) & 127;
        int k = (i >> 9) % 3;
        int g = i / 1536;
        const float* Wg = g ? Wg1 : Wg0;
        const float* av = (k == 0) ? (g ? as1 : as0)
                        : (k == 1) ? (g ? ad1 : ad0)
                        : wcls;
        const float* wrow = Wg + j * 128 + h * 32;
        const float* arow = av + h * 32;
        float sum = 0.f;
        #pragma unroll 8
        for (int c = 0; c < 32; c++) sum += wrow[c] * arow[c];
        g_v[g][k][j][h] = sum;
    }
    if (tid < 2) {
        const float* bg = tid ? bg1 : bg0;
        float s = 0.f;
        for (int j = 0; j < 128; j++) s += bg[j] * wcls[j];
        g_bgw[tid] = s;
    }
}

// ---------------------------------------------------------------------------
// prep2: g_Mt[t][o] = (W_t @ v[g][k]) transposed rows (zero-padded); row 24 = W_t@wcls;
//        g_c = b_t @ v;  g_basec = b_t @ wcls
// ---------------------------------------------------------------------------
__global__ void prep2(const float* __restrict__ W0, const float* __restrict__ b0,
                      const float* __restrict__ W1, const float* __restrict__ b1,
                      const float* __restrict__ W2, const float* __restrict__ b2,
                      const float* __restrict__ wcls,
                      int d0, int d1, int d2)
{
    int id = blockIdx.x * blockDim.x + threadIdx.x;
    int din[3] = {d0, d1, d2};
    const float* W[3] = {W0, W1, W2};
    const float* b[3] = {b0, b1, b2};
    if (id < 9216) {
        int h = id & 3;
        int i = (id >> 2) & 127;
        int k = (id >> 9) % 3;
        int g = (id / 1536) % 2;
        int t = id / 3072;
        float sum = 0.f;
        if (i < din[t]) {
            const float* Wr = W[t] + i * 128;
            #pragma unroll 8
            for (int j = 0; j < 128; j++) sum += Wr[j] * g_v[g][k][j][h];
        }
        g_Mt[t][g * 12 + k * 4 + h][i] = sum;
    } else if (id < 9216 + 384) {
        int r = id - 9216;
        int i = r & 127; int t = r >> 7;
        float s = 0.f;
        if (i < din[t]) {
            const float* Wr = W[t] + i * 128;
            #pragma unroll 8
            for (int j = 0; j < 128; j++) s += Wr[j] * wcls[j];
        }
        g_Mt[t][24][i] = s;
    } else if (id < 9216 + 384 + 72) {
        int r = id - 9600;
        int h = r & 3; int k = (r >> 2) % 3; int g = (r / 12) % 2; int t = r / 24;
        float s = 0.f;
        for (int j = 0; j < 128; j++) s += b[t][j] * g_v[g][k][j][h];
        g_c[t][g][k][h] = s;
    } else if (id < 9216 + 384 + 72 + 3) {
        int t = id - 9672;
        float s = 0.f;
        for (int j = 0; j < 128; j++) s += b[t][j] * wcls[j];
        g_basec[t] = s;
    }
}

// ---------------------------------------------------------------------------
// nodeK v2: 16 elements per lane, p = din/16 lanes per node, 32/p nodes per warp.
// Shared M tile layout sM4[o][c][r] (o<25, c<4, r<8): conflict-free broadcast
// LDS.128; reduction = log2(p) butterfly levels shared across all node groups.
// Owner lane (r==0) of each group runs the epilogue + self-loop softmax init.
// ---------------------------------------------------------------------------
__global__ void __launch_bounds__(256) nodeK(
    const float* __restrict__ x0, const float* __restrict__ x1,
    const float* __restrict__ x2, int d0, int d1, int d2, int N)
{
    int t = blockIdx.y;
    const float* x = (t == 0) ? x0 : (t == 1) ? x1 : x2;
    int din = (t == 0) ? d0 : (t == 1) ? d1 : d2;
    int p = din >> 4;                         // lanes per node (2,4,8)
    int npw = 32 / p;                         // nodes per warp
    int shift = (p == 8) ? 3 : (p == 4) ? 2 : 1;

    // Stage M: sM4 linear index = o*32 + c*8 + r  <->  g_Mt float4 index o*32 + 4r + c
    __shared__ float4 sM4[25 * 32];
    const float4* Mt4 = reinterpret_cast<const float4*>(g_Mt[t]);
    int tid = threadIdx.x;
    for (int i = tid; i < 800; i += blockDim.x) {
        int o = i >> 5;
        int c = (i >> 3) & 3;
        int r = i & 7;
        sM4[i] = Mt4[o * 32 + 4 * r + c];
    }
    __syncthreads();

    int lane = tid & 31;
    int r = lane & (p - 1);                   // element-slice index within node
    int grp = lane >> shift;                  // node group within warp
    int wid = blockIdx.x * (blockDim.x >> 5) + (tid >> 5);
    int stride = gridDim.x * (blockDim.x >> 5) * npw;

    for (int n0 = wid * npw; n0 < N; n0 += stride) {
        int node = n0 + grp;
        bool valid = node < N;

        float4 xv0, xv1, xv2, xv3;
        if (valid) {
            const float4* xr = reinterpret_cast<const float4*>(
                x + (size_t)node * din + 16 * r);
            xv0 = xr[0]; xv1 = xr[1]; xv2 = xr[2]; xv3 = xr[3];
        } else {
            xv0 = xv1 = xv2 = xv3 = make_float4(0.f, 0.f, 0.f, 0.f);
        }

        float acc[25];
        #pragma unroll
        for (int o = 0; o < 25; o++) {
            float4 m0 = sM4[o * 32 + 0 * 8 + r];
            float4 m1 = sM4[o * 32 + 1 * 8 + r];
            float4 m2 = sM4[o * 32 + 2 * 8 + r];
            float4 m3 = sM4[o * 32 + 3 * 8 + r];
            acc[o] = xv0.x * m0.x + xv0.y * m0.y + xv0.z * m0.z + xv0.w * m0.w
                   + xv1.x * m1.x + xv1.y * m1.y + xv1.z * m1.z + xv1.w * m1.w
                   + xv2.x * m2.x + xv2.y * m2.y + xv2.z * m2.z + xv2.w * m2.w
                   + xv3.x * m3.x + xv3.y * m3.y + xv3.z * m3.z + xv3.w * m3.w;
        }

        for (int off = p >> 1; off > 0; off >>= 1) {
            #pragma unroll
            for (int o = 0; o < 25; o++)
                acc[o] += __shfl_xor_sync(FULL, acc[o], off);
        }

        if (valid && r == 0) {
            #pragma unroll
            for (int gg = 0; gg < 2; gg++) {
                float ss[4], sd[4], pv[4], de[4], nu[4];
                #pragma unroll
                for (int h = 0; h < 4; h++) {
                    ss[h] = acc[gg * 12 + h]     + g_c[t][gg][0][h];
                    sd[h] = acc[gg * 12 + 4 + h] + g_c[t][gg][1][h];
                    pv[h] = acc[gg * 12 + 8 + h] + g_c[t][gg][2][h];
                    float e = ss[h] + sd[h];
                    e = e > 0.f ? e : 0.2f * e;   // leaky_relu(0.2)
                    float ex = __expf(e);
                    de[h] = ex;
                    nu[h] = ex * pv[h];
                }
                g_ssrc[t][gg][node] = make_float4(ss[0], ss[1], ss[2], ss[3]);
                g_sdst[t][gg][node] = make_float4(sd[0], sd[1], sd[2], sd[3]);
                g_p[t][gg][node]    = make_float4(pv[0], pv[1], pv[2], pv[3]);
                g_den[t][gg][node]  = make_float4(de[0], de[1], de[2], de[3]); // self-loop
                g_num[t][gg][node]  = make_float4(nu[0], nu[1], nu[2], nu[3]);
            }
            g_base[t][node] = acc[24] + g_basec[t];
        }
    }
}

// ---------------------------------------------------------------------------
// edgeK: fused over g via blockIdx.y. One pass: exp(leaky_relu(ssrc[s]+sdst[d])),
// vector RED into num/den. All per-node arrays L2-resident. Grid-stride.
// ---------------------------------------------------------------------------
__global__ void edgeK(const int* __restrict__ ei0, int E0,
                      const int* __restrict__ ei1, int E1)
{
    int g = blockIdx.y;
    const int* ei = g ? ei1 : ei0;
    int E = g ? E1 : E0;
    for (int e = blockIdx.x * blockDim.x + threadIdx.x; e < E;
         e += gridDim.x * blockDim.x) {
        int s = __ldg(&ei[e]);
        int d = __ldg(&ei[E + e]);
        #pragma unroll
        for (int t = 0; t < 3; t++) {
            float4 a  = __ldg(&g_ssrc[t][g][s]);
            float4 b  = __ldg(&g_sdst[t][g][d]);
            float4 pp = __ldg(&g_p[t][g][s]);
            float e0 = a.x + b.x, e1 = a.y + b.y, e2 = a.z + b.z, e3 = a.w + b.w;
            e0 = e0 > 0.f ? e0 : 0.2f * e0;
            e1 = e1 > 0.f ? e1 : 0.2f * e1;
            e2 = e2 > 0.f ? e2 : 0.2f * e2;
            e3 = e3 > 0.f ? e3 : 0.2f * e3;
            float x0 = __expf(e0), x1 = __expf(e1), x2 = __expf(e2), x3 = __expf(e3);
            atomicAdd(&g_den[t][g][d], make_float4(x0, x1, x2, x3));
            atomicAdd(&g_num[t][g][d], make_float4(x0 * pp.x, x1 * pp.y, x2 * pp.z, x3 * pp.w));
        }
    }
}

// ---------------------------------------------------------------------------
// finalK: out[t*N+n] = sigmoid(base + sum_g (bg.w + sum_h num/den) + b_cls)
// ---------------------------------------------------------------------------
__global__ void finalK(float* __restrict__ out, const float* __restrict__ bcls, int N)
{
    int id = blockIdx.x * blockDim.x + threadIdx.x;
    if (id >= 3 * N) return;
    int t = id / N, n = id - t * N;
    float z = g_base[t][n] + bcls[0];
    #pragma unroll
    for (int g = 0; g < 2; g++) {
        float4 nu = g_num[t][g][n];
        float4 de = g_den[t][g][n];
        z += g_bgw[g] + nu.x / de.x + nu.y / de.y + nu.z / de.z + nu.w / de.w;
    }
    out[id] = 1.f / (1.f + __expf(-z));
}

extern "C" void kernel_launch(void* const* d_in, const int* in_sizes, int n_in,
                              void* d_out, int out_size)
{
    const float* x_acc = (const float*)d_in[0];
    const float* x_cus = (const float*)d_in[1];
    const float* x_txn = (const float*)d_in[2];
    // d_in[3] = ei_transacts: dead code in the reference
    const int*   ei_ow = (const int*)d_in[4];
    const int*   ei_sh = (const int*)d_in[5];
    const float* W_acc = (const float*)d_in[6];  const float* b_acc = (const float*)d_in[7];
    const float* W_cus = (const float*)d_in[8];  const float* b_cus = (const float*)d_in[9];
    const float* W_txn = (const float*)d_in[10]; const float* b_txn = (const float*)d_in[11];
    const float* Wg_ow = (const float*)d_in[12]; const float* as_ow = (const float*)d_in[13];
    const float* ad_ow = (const float*)d_in[14]; const float* bg_ow = (const float*)d_in[15];
    const float* Wg_sh = (const float*)d_in[16]; const float* as_sh = (const float*)d_in[17];
    const float* ad_sh = (const float*)d_in[18]; const float* bg_sh = (const float*)d_in[19];
    const float* W_cls = (const float*)d_in[20]; const float* b_cls = (const float*)d_in[21];
    float* out = (float*)d_out;

    int HIDv = in_sizes[7];               // 128
    int d0 = in_sizes[6] / HIDv;          // 64
    int d1 = in_sizes[8] / HIDv;          // 32
    int d2 = in_sizes[10] / HIDv;         // 128
    int N  = in_sizes[0] / d0;            // 50000
    int E_ow = in_sizes[4] / 2;
    int E_sh = in_sizes[5] / 2;

    prep1<<<1, 256>>>(Wg_ow, as_ow, ad_ow, bg_ow, Wg_sh, as_sh, ad_sh, bg_sh, W_cls);
    prep2<<<(9675 + 127) / 128, 128>>>(W_acc, b_acc, W_cus, b_cus, W_txn, b_txn, W_cls,
                                       d0, d1, d2);
    dim3 ngrid(148, 3);
    nodeK<<<ngrid, 256>>>(x_acc, x_cus, x_txn, d0, d1, d2, N);
    dim3 egrid(1184, 2);
    edgeK<<<egrid, 256>>>(ei_ow, E_ow, ei_sh, E_sh);
    finalK<<<(3 * N + 255) / 256, 256>>>(out, b_cls, N);
}

// round 15
// speedup vs baseline: 2.3133x; 1.3313x over previous
#include <cuda_runtime.h>
#include <math.h>

#define NMAX 65536
#define FULL 0xFFFFFFFFu

// Packed per-node records (128B-aligned lines; L2-resident ~40MB total).
// g_sp [g][n]: slots 0..2 = ssrc[t], 3..5 = p[t]
// g_sd [g][n]: slots 0..2 = sdst[t]
// g_acc[g][n]: slots 2t = den[t], 2t+1 = num[t]
__device__ __align__(128) float4 g_sp [2][NMAX][8];
__device__ __align__(128) float4 g_sd [2][NMAX][4];
__device__ __align__(128) float4 g_acc[2][NMAX][8];
__device__ float  g_base[3][NMAX];

// Small composed parameter tensors
__device__ float g_v[2][3][128][4];      // [g][kind(src,dst,p)][j][h] = per-head Wg@att
// g_Mt[t][o][j]: o = g*12 + k*4 + h for o<24; o==24 = W_t@W_cls. Zero-padded j>=din.
__device__ __align__(16) float g_Mt[3][25][128];
__device__ float g_c[3][2][3][4];        // b_t @ v
__device__ float g_basec[3];             // b_t @ W_cls
__device__ float g_bgw[2];               // bg_g @ W_cls

// ---------------------------------------------------------------------------
// prep1 (multi-block): v[g][k][j][h] = sum_c Wg_g[j, h*32+c] * att[h*32+c]
// ---------------------------------------------------------------------------
__global__ void prep1(const float* __restrict__ Wg0, const float* __restrict__ as0,
                      const float* __restrict__ ad0, const float* __restrict__ bg0,
                      const float* __restrict__ Wg1, const float* __restrict__ as1,
                      const float* __restrict__ ad1, const float* __restrict__ bg1,
                      const float* __restrict__ wcls)
{
    int id = blockIdx.x * blockDim.x + threadIdx.x;
    if (id < 3072) {
        int h = id & 3;
        int j = (id >> 2) & 127;
        int k = (id >> 9) % 3;
        int g = id / 1536;
        const float* Wg = g ? Wg1 : Wg0;
        const float* av = (k == 0) ? (g ? as1 : as0)
                        : (k == 1) ? (g ? ad1 : ad0)
                        : wcls;
        const float* wrow = Wg + j * 128 + h * 32;
        const float* arow = av + h * 32;
        float sum = 0.f;
        #pragma unroll 8
        for (int c = 0; c < 32; c++) sum += wrow[c] * arow[c];
        g_v[g][k][j][h] = sum;
    } else if (id < 3074) {
        const float* bg = (id - 3072) ? bg1 : bg0;
        float s = 0.f;
        for (int j = 0; j < 128; j++) s += bg[j] * wcls[j];
        g_bgw[id - 3072] = s;
    }
}

// ---------------------------------------------------------------------------
// prep2: g_Mt[t][o] = (W_t @ v[g][k]) transposed rows (zero-padded); row 24 = W_t@wcls;
//        g_c = b_t @ v;  g_basec = b_t @ wcls
// ---------------------------------------------------------------------------
__global__ void prep2(const float* __restrict__ W0, const float* __restrict__ b0,
                      const float* __restrict__ W1, const float* __restrict__ b1,
                      const float* __restrict__ W2, const float* __restrict__ b2,
                      const float* __restrict__ wcls,
                      int d0, int d1, int d2)
{
    int id = blockIdx.x * blockDim.x + threadIdx.x;
    int din[3] = {d0, d1, d2};
    const float* W[3] = {W0, W1, W2};
    const float* b[3] = {b0, b1, b2};
    if (id < 9216) {
        int h = id & 3;
        int i = (id >> 2) & 127;
        int k = (id >> 9) % 3;
        int g = (id / 1536) % 2;
        int t = id / 3072;
        float sum = 0.f;
        if (i < din[t]) {
            const float* Wr = W[t] + i * 128;
            #pragma unroll 8
            for (int j = 0; j < 128; j++) sum += Wr[j] * g_v[g][k][j][h];
        }
        g_Mt[t][g * 12 + k * 4 + h][i] = sum;
    } else if (id < 9216 + 384) {
        int r = id - 9216;
        int i = r & 127; int t = r >> 7;
        float s = 0.f;
        if (i < din[t]) {
            const float* Wr = W[t] + i * 128;
            #pragma unroll 8
            for (int j = 0; j < 128; j++) s += Wr[j] * wcls[j];
        }
        g_Mt[t][24][i] = s;
    } else if (id < 9216 + 384 + 72) {
        int r = id - 9600;
        int h = r & 3; int k = (r >> 2) % 3; int g = (r / 12) % 2; int t = r / 24;
        float s = 0.f;
        for (int j = 0; j < 128; j++) s += b[t][j] * g_v[g][k][j][h];
        g_c[t][g][k][h] = s;
    } else if (id < 9216 + 384 + 72 + 3) {
        int t = id - 9672;
        float s = 0.f;
        for (int j = 0; j < 128; j++) s += b[t][j] * wcls[j];
        g_basec[t] = s;
    }
}

// ---------------------------------------------------------------------------
// nodeK v2: 16 elements per lane, p = din/16 lanes per node, 32/p nodes per warp.
// Conflict-free broadcast LDS.128 of M tile; log2(p) butterfly reduction.
// Owner lane stores into packed-by-t layouts + self-loop softmax init.
// ---------------------------------------------------------------------------
__global__ void __launch_bounds__(256) nodeK(
    const float* __restrict__ x0, const float* __restrict__ x1,
    const float* __restrict__ x2, int d0, int d1, int d2, int N)
{
    int t = blockIdx.y;
    const float* x = (t == 0) ? x0 : (t == 1) ? x1 : x2;
    int din = (t == 0) ? d0 : (t == 1) ? d1 : d2;
    int p = din >> 4;                         // lanes per node (2,4,8)
    int npw = 32 / p;                         // nodes per warp
    int shift = (p == 8) ? 3 : (p == 4) ? 2 : 1;

    // Stage M: sM4 linear index = o*32 + c*8 + r  <->  g_Mt float4 index o*32 + 4r + c
    __shared__ float4 sM4[25 * 32];
    const float4* Mt4 = reinterpret_cast<const float4*>(g_Mt[t]);
    int tid = threadIdx.x;
    for (int i = tid; i < 800; i += blockDim.x) {
        int o = i >> 5;
        int c = (i >> 3) & 3;
        int r = i & 7;
        sM4[i] = Mt4[o * 32 + 4 * r + c];
    }
    __syncthreads();

    int lane = tid & 31;
    int r = lane & (p - 1);                   // element-slice index within node
    int grp = lane >> shift;                  // node group within warp
    int wid = blockIdx.x * (blockDim.x >> 5) + (tid >> 5);
    int stride = gridDim.x * (blockDim.x >> 5) * npw;

    for (int n0 = wid * npw; n0 < N; n0 += stride) {
        int node = n0 + grp;
        bool valid = node < N;

        float4 xv0, xv1, xv2, xv3;
        if (valid) {
            const float4* xr = reinterpret_cast<const float4*>(
                x + (size_t)node * din + 16 * r);
            xv0 = xr[0]; xv1 = xr[1]; xv2 = xr[2]; xv3 = xr[3];
        } else {
            xv0 = xv1 = xv2 = xv3 = make_float4(0.f, 0.f, 0.f, 0.f);
        }

        float acc[25];
        #pragma unroll
        for (int o = 0; o < 25; o++) {
            float4 m0 = sM4[o * 32 + 0 * 8 + r];
            float4 m1 = sM4[o * 32 + 1 * 8 + r];
            float4 m2 = sM4[o * 32 + 2 * 8 + r];
            float4 m3 = sM4[o * 32 + 3 * 8 + r];
            acc[o] = xv0.x * m0.x + xv0.y * m0.y + xv0.z * m0.z + xv0.w * m0.w
                   + xv1.x * m1.x + xv1.y * m1.y + xv1.z * m1.z + xv1.w * m1.w
                   + xv2.x * m2.x + xv2.y * m2.y + xv2.z * m2.z + xv2.w * m2.w
                   + xv3.x * m3.x + xv3.y * m3.y + xv3.z * m3.z + xv3.w * m3.w;
        }

        for (int off = p >> 1; off > 0; off >>= 1) {
            #pragma unroll
            for (int o = 0; o < 25; o++)
                acc[o] += __shfl_xor_sync(FULL, acc[o], off);
        }

        if (valid && r == 0) {
            #pragma unroll
            for (int gg = 0; gg < 2; gg++) {
                float ss[4], sd[4], pv[4], de[4], nu[4];
                #pragma unroll
                for (int h = 0; h < 4; h++) {
                    ss[h] = acc[gg * 12 + h]     + g_c[t][gg][0][h];
                    sd[h] = acc[gg * 12 + 4 + h] + g_c[t][gg][1][h];
                    pv[h] = acc[gg * 12 + 8 + h] + g_c[t][gg][2][h];
                    float e = ss[h] + sd[h];
                    e = e > 0.f ? e : 0.2f * e;   // leaky_relu(0.2)
                    float ex = __expf(e);
                    de[h] = ex;
                    nu[h] = ex * pv[h];
                }
                g_sp[gg][node][t]     = make_float4(ss[0], ss[1], ss[2], ss[3]);
                g_sp[gg][node][3 + t] = make_float4(pv[0], pv[1], pv[2], pv[3]);
                g_sd[gg][node][t]     = make_float4(sd[0], sd[1], sd[2], sd[3]);
                g_acc[gg][node][2 * t]     = make_float4(de[0], de[1], de[2], de[3]); // self-loop
                g_acc[gg][node][2 * t + 1] = make_float4(nu[0], nu[1], nu[2], nu[3]);
            }
            g_base[t][node] = acc[24] + g_basec[t];
        }
    }
}

// ---------------------------------------------------------------------------
// edgeK: fused over g via blockIdx.y. Packed-by-t records: 3 sectors s-side,
// 2 sectors d-side, 3 RMW sectors for the 6 float4 atomics. Grid-stride.
// ---------------------------------------------------------------------------
__global__ void edgeK(const int* __restrict__ ei0, int E0,
                      const int* __restrict__ ei1, int E1)
{
    int g = blockIdx.y;
    const int* ei = g ? ei1 : ei0;
    int E = g ? E1 : E0;
    for (int e = blockIdx.x * blockDim.x + threadIdx.x; e < E;
         e += gridDim.x * blockDim.x) {
        int s = __ldg(&ei[e]);
        int d = __ldg(&ei[E + e]);
        const float4* sp = g_sp[g][s];
        const float4* sdp = g_sd[g][d];
        float4* ac = g_acc[g][d];
        float4 a0 = __ldg(sp + 0), a1 = __ldg(sp + 1), a2 = __ldg(sp + 2);
        float4 p0 = __ldg(sp + 3), p1 = __ldg(sp + 4), p2 = __ldg(sp + 5);
        float4 b0 = __ldg(sdp + 0), b1 = __ldg(sdp + 1), b2 = __ldg(sdp + 2);
        float4 av[3] = {a0, a1, a2};
        float4 pv[3] = {p0, p1, p2};
        float4 bv[3] = {b0, b1, b2};
        #pragma unroll
        for (int t = 0; t < 3; t++) {
            float e0 = av[t].x + bv[t].x, e1 = av[t].y + bv[t].y;
            float e2 = av[t].z + bv[t].z, e3 = av[t].w + bv[t].w;
            e0 = e0 > 0.f ? e0 : 0.2f * e0;
            e1 = e1 > 0.f ? e1 : 0.2f * e1;
            e2 = e2 > 0.f ? e2 : 0.2f * e2;
            e3 = e3 > 0.f ? e3 : 0.2f * e3;
            float x0 = __expf(e0), x1 = __expf(e1), x2 = __expf(e2), x3 = __expf(e3);
            atomicAdd(ac + 2 * t,     make_float4(x0, x1, x2, x3));
            atomicAdd(ac + 2 * t + 1, make_float4(x0 * pv[t].x, x1 * pv[t].y,
                                                  x2 * pv[t].z, x3 * pv[t].w));
        }
    }
}

// ---------------------------------------------------------------------------
// finalK: out[t*N+n] = sigmoid(base + sum_g (bg.w + sum_h num/den) + b_cls)
// ---------------------------------------------------------------------------
__global__ void finalK(float* __restrict__ out, const float* __restrict__ bcls, int N)
{
    int id = blockIdx.x * blockDim.x + threadIdx.x;
    if (id >= 3 * N) return;
    int t = id / N, n = id - t * N;
    float z = g_base[t][n] + bcls[0];
    #pragma unroll
    for (int g = 0; g < 2; g++) {
        float4 de = g_acc[g][n][2 * t];
        float4 nu = g_acc[g][n][2 * t + 1];
        z += g_bgw[g] + nu.x / de.x + nu.y / de.y + nu.z / de.z + nu.w / de.w;
    }
    out[id] = 1.f / (1.f + __expf(-z));
}

extern "C" void kernel_launch(void* const* d_in, const int* in_sizes, int n_in,
                              void* d_out, int out_size)
{
    const float* x_acc = (const float*)d_in[0];
    const float* x_cus = (const float*)d_in[1];
    const float* x_txn = (const float*)d_in[2];
    // d_in[3] = ei_transacts: dead code in the reference
    const int*   ei_ow = (const int*)d_in[4];
    const int*   ei_sh = (const int*)d_in[5];
    const float* W_acc = (const float*)d_in[6];  const float* b_acc = (const float*)d_in[7];
    const float* W_cus = (const float*)d_in[8];  const float* b_cus = (const float*)d_in[9];
    const float* W_txn = (const float*)d_in[10]; const float* b_txn = (const float*)d_in[11];
    const float* Wg_ow = (const float*)d_in[12]; const float* as_ow = (const float*)d_in[13];
    const float* ad_ow = (const float*)d_in[14]; const float* bg_ow = (const float*)d_in[15];
    const float* Wg_sh = (const float*)d_in[16]; const float* as_sh = (const float*)d_in[17];
    const float* ad_sh = (const float*)d_in[18]; const float* bg_sh = (const float*)d_in[19];
    const float* W_cls = (const float*)d_in[20]; const float* b_cls = (const float*)d_in[21];
    float* out = (float*)d_out;

    int HIDv = in_sizes[7];               // 128
    int d0 = in_sizes[6] / HIDv;          // 64
    int d1 = in_sizes[8] / HIDv;          // 32
    int d2 = in_sizes[10] / HIDv;         // 128
    int N  = in_sizes[0] / d0;            // 50000
    int E_ow = in_sizes[4] / 2;
    int E_sh = in_sizes[5] / 2;

    prep1<<<13, 256>>>(Wg_ow, as_ow, ad_ow, bg_ow, Wg_sh, as_sh, ad_sh, bg_sh, W_cls);
    prep2<<<(9675 + 127) / 128, 128>>>(W_acc, b_acc, W_cus, b_cus, W_txn, b_txn, W_cls,
                                       d0, d1, d2);
    dim3 ngrid(148, 3);
    nodeK<<<ngrid, 256>>>(x_acc, x_cus, x_txn, d0, d1, d2, N);
    dim3 egrid(1184, 2);
    edgeK<<<egrid, 256>>>(ei_ow, E_ow, ei_sh, E_sh);
    finalK<<<(3 * N + 255) / 256, 256>>>(out, b_cls, N);
}

// round 16
// speedup vs baseline: 2.8401x; 1.2277x over previous
#include <cuda_runtime.h>
#include <math.h>

#define NMAX 65536
#define FULL 0xFFFFFFFFu

// Packed per-node records (128B-aligned lines; L2-resident ~40MB total).
// g_sp [g][n]: slots 0..2 = ssrc[t], 3..5 = p[t]
// g_sd [g][n]: slots 0..2 = sdst[t]
// g_acc[g][n]: slots 2t = den[t], 2t+1 = num[t]
__device__ __align__(128) float4 g_sp [2][NMAX][8];
__device__ __align__(128) float4 g_sd [2][NMAX][4];
__device__ __align__(128) float4 g_acc[2][NMAX][8];
__device__ float  g_base[3][NMAX];

// Small composed parameter tensors
__device__ float g_v[2][3][128][4];      // [g][kind(src,dst,p)][j][h] = per-head Wg@att
// g_Mt[t][o][j]: o = g*12 + k*4 + h for o<24; o==24 = W_t@W_cls. Zero-padded j>=din.
__device__ __align__(16) float g_Mt[3][25][128];
__device__ float g_c[3][2][3][4];        // b_t @ v
__device__ float g_basec[3];             // b_t @ W_cls
__device__ float g_bgw[2];               // bg_g @ W_cls

// ---------------------------------------------------------------------------
// prep1 (multi-block): v[g][k][j][h] = sum_c Wg_g[j, h*32+c] * att[h*32+c]
// ---------------------------------------------------------------------------
__global__ void prep1(const float* __restrict__ Wg0, const float* __restrict__ as0,
                      const float* __restrict__ ad0, const float* __restrict__ bg0,
                      const float* __restrict__ Wg1, const float* __restrict__ as1,
                      const float* __restrict__ ad1, const float* __restrict__ bg1,
                      const float* __restrict__ wcls)
{
    int id = blockIdx.x * blockDim.x + threadIdx.x;
    if (id < 3072) {
        int h = id & 3;
        int j = (id >> 2) & 127;
        int k = (id >> 9) % 3;
        int g = id / 1536;
        const float* Wg = g ? Wg1 : Wg0;
        const float* av = (k == 0) ? (g ? as1 : as0)
                        : (k == 1) ? (g ? ad1 : ad0)
                        : wcls;
        const float* wrow = Wg + j * 128 + h * 32;
        const float* arow = av + h * 32;
        float sum = 0.f;
        #pragma unroll 8
        for (int c = 0; c < 32; c++) sum += wrow[c] * arow[c];
        g_v[g][k][j][h] = sum;
    } else if (id < 3074) {
        const float* bg = (id - 3072) ? bg1 : bg0;
        float s = 0.f;
        for (int j = 0; j < 128; j++) s += bg[j] * wcls[j];
        g_bgw[id - 3072] = s;
    }
}

// ---------------------------------------------------------------------------
// prep2: g_Mt[t][o] = (W_t @ v[g][k]) transposed rows (zero-padded); row 24 = W_t@wcls;
//        g_c = b_t @ v;  g_basec = b_t @ wcls
// ---------------------------------------------------------------------------
__global__ void prep2(const float* __restrict__ W0, const float* __restrict__ b0,
                      const float* __restrict__ W1, const float* __restrict__ b1,
                      const float* __restrict__ W2, const float* __restrict__ b2,
                      const float* __restrict__ wcls,
                      int d0, int d1, int d2)
{
    int id = blockIdx.x * blockDim.x + threadIdx.x;
    int din[3] = {d0, d1, d2};
    const float* W[3] = {W0, W1, W2};
    const float* b[3] = {b0, b1, b2};
    if (id < 9216) {
        int h = id & 3;
        int i = (id >> 2) & 127;
        int k = (id >> 9) % 3;
        int g = (id / 1536) % 2;
        int t = id / 3072;
        float sum = 0.f;
        if (i < din[t]) {
            const float* Wr = W[t] + i * 128;
            #pragma unroll 8
            for (int j = 0; j < 128; j++) sum += Wr[j] * g_v[g][k][j][h];
        }
        g_Mt[t][g * 12 + k * 4 + h][i] = sum;
    } else if (id < 9216 + 384) {
        int r = id - 9216;
        int i = r & 127; int t = r >> 7;
        float s = 0.f;
        if (i < din[t]) {
            const float* Wr = W[t] + i * 128;
            #pragma unroll 8
            for (int j = 0; j < 128; j++) s += Wr[j] * wcls[j];
        }
        g_Mt[t][24][i] = s;
    } else if (id < 9216 + 384 + 72) {
        int r = id - 9600;
        int h = r & 3; int k = (r >> 2) % 3; int g = (r / 12) % 2; int t = r / 24;
        float s = 0.f;
        for (int j = 0; j < 128; j++) s += b[t][j] * g_v[g][k][j][h];
        g_c[t][g][k][h] = s;
    } else if (id < 9216 + 384 + 72 + 3) {
        int t = id - 9672;
        float s = 0.f;
        for (int j = 0; j < 128; j++) s += b[t][j] * wcls[j];
        g_basec[t] = s;
    }
}

// ---------------------------------------------------------------------------
// nodeK v2: 16 elements per lane, p = din/16 lanes per node, 32/p nodes per warp.
// Conflict-free broadcast LDS.128 of M tile; log2(p) butterfly reduction.
// Owner lane stores into packed-by-t layouts + self-loop softmax init.
// ---------------------------------------------------------------------------
__global__ void __launch_bounds__(256) nodeK(
    const float* __restrict__ x0, const float* __restrict__ x1,
    const float* __restrict__ x2, int d0, int d1, int d2, int N)
{
    int t = blockIdx.y;
    const float* x = (t == 0) ? x0 : (t == 1) ? x1 : x2;
    int din = (t == 0) ? d0 : (t == 1) ? d1 : d2;
    int p = din >> 4;                         // lanes per node (2,4,8)
    int npw = 32 / p;                         // nodes per warp
    int shift = (p == 8) ? 3 : (p == 4) ? 2 : 1;

    // Stage M: sM4 linear index = o*32 + c*8 + r  <->  g_Mt float4 index o*32 + 4r + c
    __shared__ float4 sM4[25 * 32];
    const float4* Mt4 = reinterpret_cast<const float4*>(g_Mt[t]);
    int tid = threadIdx.x;
    for (int i = tid; i < 800; i += blockDim.x) {
        int o = i >> 5;
        int c = (i >> 3) & 3;
        int r = i & 7;
        sM4[i] = Mt4[o * 32 + 4 * r + c];
    }
    __syncthreads();

    int lane = tid & 31;
    int r = lane & (p - 1);                   // element-slice index within node
    int grp = lane >> shift;                  // node group within warp
    int wid = blockIdx.x * (blockDim.x >> 5) + (tid >> 5);
    int stride = gridDim.x * (blockDim.x >> 5) * npw;

    for (int n0 = wid * npw; n0 < N; n0 += stride) {
        int node = n0 + grp;
        bool valid = node < N;

        float4 xv0, xv1, xv2, xv3;
        if (valid) {
            const float4* xr = reinterpret_cast<const float4*>(
                x + (size_t)node * din + 16 * r);
            xv0 = xr[0]; xv1 = xr[1]; xv2 = xr[2]; xv3 = xr[3];
        } else {
            xv0 = xv1 = xv2 = xv3 = make_float4(0.f, 0.f, 0.f, 0.f);
        }

        float acc[25];
        #pragma unroll
        for (int o = 0; o < 25; o++) {
            float4 m0 = sM4[o * 32 + 0 * 8 + r];
            float4 m1 = sM4[o * 32 + 1 * 8 + r];
            float4 m2 = sM4[o * 32 + 2 * 8 + r];
            float4 m3 = sM4[o * 32 + 3 * 8 + r];
            acc[o] = xv0.x * m0.x + xv0.y * m0.y + xv0.z * m0.z + xv0.w * m0.w
                   + xv1.x * m1.x + xv1.y * m1.y + xv1.z * m1.z + xv1.w * m1.w
                   + xv2.x * m2.x + xv2.y * m2.y + xv2.z * m2.z + xv2.w * m2.w
                   + xv3.x * m3.x + xv3.y * m3.y + xv3.z * m3.z + xv3.w * m3.w;
        }

        for (int off = p >> 1; off > 0; off >>= 1) {
            #pragma unroll
            for (int o = 0; o < 25; o++)
                acc[o] += __shfl_xor_sync(FULL, acc[o], off);
        }

        if (valid && r == 0) {
            #pragma unroll
            for (int gg = 0; gg < 2; gg++) {
                float ss[4], sd[4], pv[4], de[4], nu[4];
                #pragma unroll
                for (int h = 0; h < 4; h++) {
                    ss[h] = acc[gg * 12 + h]     + g_c[t][gg][0][h];
                    sd[h] = acc[gg * 12 + 4 + h] + g_c[t][gg][1][h];
                    pv[h] = acc[gg * 12 + 8 + h] + g_c[t][gg][2][h];
                    float e = ss[h] + sd[h];
                    e = e > 0.f ? e : 0.2f * e;   // leaky_relu(0.2)
                    float ex = __expf(e);
                    de[h] = ex;
                    nu[h] = ex * pv[h];
                }
                g_sp[gg][node][t]     = make_float4(ss[0], ss[1], ss[2], ss[3]);
                g_sp[gg][node][3 + t] = make_float4(pv[0], pv[1], pv[2], pv[3]);
                g_sd[gg][node][t]     = make_float4(sd[0], sd[1], sd[2], sd[3]);
                g_acc[gg][node][2 * t]     = make_float4(de[0], de[1], de[2], de[3]); // self-loop
                g_acc[gg][node][2 * t + 1] = make_float4(nu[0], nu[1], nu[2], nu[3]);
            }
            g_base[t][node] = acc[24] + g_basec[t];
        }
    }
}

// ---------------------------------------------------------------------------
// edgeK v3: 4 lanes per edge (8 edges/warp). Each gather instruction touches
// only 8 distinct 128B records -> ~6 L1tex wavefronts/edge (was 17).
// Lane c of each group: round1 loads slot c (ss0,ss1,ss2,p0); round2 loads
// slot 4+c for c<2 (p1,p2); sd slot c for c<3. p redistributed by one rotate
// shfl. Lane t (0..2) computes head-vector t and fires den/num atomics.
// ---------------------------------------------------------------------------
__global__ void edgeK(const int* __restrict__ ei0, int E0,
                      const int* __restrict__ ei1, int E1)
{
    int g = blockIdx.y;
    const int* ei = g ? ei1 : ei0;
    int E = g ? E1 : E0;
    int tid = threadIdx.x;
    int lane = tid & 31;
    int c = lane & 3;                 // slot lane within edge group
    int sub = lane >> 2;              // edge index within warp (0..7)
    int wpb = blockDim.x >> 5;
    int gw = blockIdx.x * wpb + (tid >> 5);
    int nw = gridDim.x * wpb;
    int srcl = (lane & ~3) + ((c == 0) ? 3 : c - 1);   // rotate source for p

    for (int base = gw * 8; base < E; base += nw * 8) {
        int e = base + sub;
        bool v = e < E;
        int s = 0, d = 0;
        if (v) { s = __ldg(&ei[e]); d = __ldg(&ei[E + e]); }

        const float4* sp = g_sp[g][s];
        float4 r1 = make_float4(0.f, 0.f, 0.f, 0.f);
        float4 r2 = make_float4(0.f, 0.f, 0.f, 0.f);
        float4 sd = make_float4(0.f, 0.f, 0.f, 0.f);
        if (v)          r1 = __ldg(sp + c);            // ss0|ss1|ss2|p0
        if (v && c < 2) r2 = __ldg(sp + 4 + c);        // p1|p2
        if (v && c < 3) sd = __ldg(&g_sd[g][d][c]);    // sd_c

        // p_t for lane t: t=0 <- lane3.r1, t=1 <- lane0.r2, t=2 <- lane1.r2
        float4 q1, q2, pv;
        q1.x = __shfl_sync(FULL, r1.x, srcl);
        q1.y = __shfl_sync(FULL, r1.y, srcl);
        q1.z = __shfl_sync(FULL, r1.z, srcl);
        q1.w = __shfl_sync(FULL, r1.w, srcl);
        q2.x = __shfl_sync(FULL, r2.x, srcl);
        q2.y = __shfl_sync(FULL, r2.y, srcl);
        q2.z = __shfl_sync(FULL, r2.z, srcl);
        q2.w = __shfl_sync(FULL, r2.w, srcl);
        pv = (c == 0) ? q1 : q2;

        if (v && c < 3) {
            float e0 = r1.x + sd.x, e1 = r1.y + sd.y;
            float e2 = r1.z + sd.z, e3 = r1.w + sd.w;
            e0 = e0 > 0.f ? e0 : 0.2f * e0;
            e1 = e1 > 0.f ? e1 : 0.2f * e1;
            e2 = e2 > 0.f ? e2 : 0.2f * e2;
            e3 = e3 > 0.f ? e3 : 0.2f * e3;
            float x0 = __expf(e0), x1 = __expf(e1), x2 = __expf(e2), x3 = __expf(e3);
            float4* ac = g_acc[g][d];
            atomicAdd(ac + 2 * c,     make_float4(x0, x1, x2, x3));
            atomicAdd(ac + 2 * c + 1, make_float4(x0 * pv.x, x1 * pv.y,
                                                  x2 * pv.z, x3 * pv.w));
        }
    }
}

// ---------------------------------------------------------------------------
// finalK: out[t*N+n] = sigmoid(base + sum_g (bg.w + sum_h num/den) + b_cls)
// ---------------------------------------------------------------------------
__global__ void finalK(float* __restrict__ out, const float* __restrict__ bcls, int N)
{
    int id = blockIdx.x * blockDim.x + threadIdx.x;
    if (id >= 3 * N) return;
    int t = id / N, n = id - t * N;
    float z = g_base[t][n] + bcls[0];
    #pragma unroll
    for (int g = 0; g < 2; g++) {
        float4 de = g_acc[g][n][2 * t];
        float4 nu = g_acc[g][n][2 * t + 1];
        z += g_bgw[g] + nu.x / de.x + nu.y / de.y + nu.z / de.z + nu.w / de.w;
    }
    out[id] = 1.f / (1.f + __expf(-z));
}

extern "C" void kernel_launch(void* const* d_in, const int* in_sizes, int n_in,
                              void* d_out, int out_size)
{
    const float* x_acc = (const float*)d_in[0];
    const float* x_cus = (const float*)d_in[1];
    const float* x_txn = (const float*)d_in[2];
    // d_in[3] = ei_transacts: dead code in the reference
    const int*   ei_ow = (const int*)d_in[4];
    const int*   ei_sh = (const int*)d_in[5];
    const float* W_acc = (const float*)d_in[6];  const float* b_acc = (const float*)d_in[7];
    const float* W_cus = (const float*)d_in[8];  const float* b_cus = (const float*)d_in[9];
    const float* W_txn = (const float*)d_in[10]; const float* b_txn = (const float*)d_in[11];
    const float* Wg_ow = (const float*)d_in[12]; const float* as_ow = (const float*)d_in[13];
    const float* ad_ow = (const float*)d_in[14]; const float* bg_ow = (const float*)d_in[15];
    const float* Wg_sh = (const float*)d_in[16]; const float* as_sh = (const float*)d_in[17];
    const float* ad_sh = (const float*)d_in[18]; const float* bg_sh = (const float*)d_in[19];
    const float* W_cls = (const float*)d_in[20]; const float* b_cls = (const float*)d_in[21];
    float* out = (float*)d_out;

    int HIDv = in_sizes[7];               // 128
    int d0 = in_sizes[6] / HIDv;          // 64
    int d1 = in_sizes[8] / HIDv;          // 32
    int d2 = in_sizes[10] / HIDv;         // 128
    int N  = in_sizes[0] / d0;            // 50000
    int E_ow = in_sizes[4] / 2;
    int E_sh = in_sizes[5] / 2;

    prep1<<<13, 256>>>(Wg_ow, as_ow, ad_ow, bg_ow, Wg_sh, as_sh, ad_sh, bg_sh, W_cls);
    prep2<<<(9675 + 127) / 128, 128>>>(W_acc, b_acc, W_cus, b_cus, W_txn, b_txn, W_cls,
                                       d0, d1, d2);
    dim3 ngrid(148, 3);
    nodeK<<<ngrid, 256>>>(x_acc, x_cus, x_txn, d0, d1, d2, N);
    dim3 egrid(1184, 2);
    edgeK<<<egrid, 256>>>(ei_ow, E_ow, ei_sh, E_sh);
    finalK<<<(3 * N + 255) / 256, 256>>>(out, b_cls, N);
}